// round 5
// baseline (speedup 1.0000x reference)
#include <cuda_runtime.h>
#include <cstddef>

#define N_NODES 20000
#define N_EDGES 160000
#define D_IN    512
#define D_LAT   512
#define D_OUT   256
#define L_LAYERS 3

// ---------------------------------------------------------------------------
// Scratch: module-static __device__ arrays (sanctioned by harness rules).
// Referenced directly from device code; kernel_launch is launches-only.
// ---------------------------------------------------------------------------
__device__ __align__(16) float  g_h[2][(size_t)N_NODES * D_LAT];
__device__ __align__(16) float  g_agg[(size_t)N_NODES * D_LAT];
__device__ float  g_deg[N_NODES];
__device__ float4 g_edge[N_EDGES];   // {src_bits, dst_bits, inv_norm, 0}
__device__ int    g_el64;            // 1 if edge_list is int64, 0 if int32

// ---------------------------------------------------------------------------
// Detect edge_list dtype. Reference says int64, but JAX default (x64 off)
// materializes int32. For little-endian int64 with values < 20000, every odd
// 32-bit word is the zero high-half; for int32 pairs, odd words are random
// dst indices. Checking 256 odd words makes misdetection P ~ 20000^-256.
// ---------------------------------------------------------------------------
__global__ void detect_kernel(const int* __restrict__ el32) {
    if (threadIdx.x == 0) {
        int any = 0;
        for (int i = 0; i < 256; i++) any |= el32[2 * i + 1];
        g_el64 = (any == 0) ? 1 : 0;
    }
}

__device__ __forceinline__ void load_edge(const void* __restrict__ el,
                                          int e, int& s, int& d) {
    if (g_el64) {
        const long long* p = (const long long*)el;
        s = (int)p[2 * e + 0];
        d = (int)p[2 * e + 1];
    } else {
        const int* p = (const int*)el;
        s = p[2 * e + 0];
        d = p[2 * e + 1];
    }
}

// ---------------------------------------------------------------------------
// Zeroing kernels (write statics directly)
// ---------------------------------------------------------------------------
__global__ void zero_deg_kernel() {
    int i = blockIdx.x * blockDim.x + threadIdx.x;
    if (i < N_NODES) g_deg[i] = 0.0f;
}

__global__ void zero_agg_kernel() {
    const int n4 = (int)((size_t)N_NODES * D_LAT / 4);
    float4* p = (float4*)g_agg;
    float4 z = make_float4(0.f, 0.f, 0.f, 0.f);
    int stride = gridDim.x * blockDim.x;
    for (int i = blockIdx.x * blockDim.x + threadIdx.x; i < n4; i += stride)
        p[i] = z;
}

// ---------------------------------------------------------------------------
// Degree (in-degree over dst), then packed edge records
// ---------------------------------------------------------------------------
__global__ void deg_kernel(const void* __restrict__ el) {
    int e = blockIdx.x * blockDim.x + threadIdx.x;
    if (e < N_EDGES) {
        int s, d;
        load_edge(el, e, s, d);
        atomicAdd(&g_deg[d], 1.0f);
    }
}

__global__ void edgeprep_kernel(const void* __restrict__ el) {
    int e = blockIdx.x * blockDim.x + threadIdx.x;
    if (e < N_EDGES) {
        int s, d;
        load_edge(el, e, s, d);
        float w = rsqrtf((g_deg[d] + 1.0f) * (g_deg[s] + 1.0f));
        float4 r;
        r.x = __int_as_float(s);
        r.y = __int_as_float(d);
        r.z = w;
        r.w = 0.0f;
        g_edge[e] = r;
    }
}

// ---------------------------------------------------------------------------
// Edge scatter: g_agg[dst] += g_h[hsel][src] * inv_norm[e].
// One warp per edge, 16 floats/lane, float4 gathers + scalar atomics.
// h and agg (40 MB each) largely fit in L2 -> L2-atomic bound.
// ---------------------------------------------------------------------------
__global__ void scatter_kernel(int hsel) {
    int gt = blockIdx.x * blockDim.x + threadIdx.x;
    int e = gt >> 5;
    int lane = gt & 31;
    if (e >= N_EDGES) return;
    float4 r = g_edge[e];
    int s = __float_as_int(r.x);
    int d = __float_as_int(r.y);
    float w = r.z;
    const float* h = g_h[hsel];
    const float4* hs = (const float4*)(h + (size_t)s * D_LAT);
    float* ag = g_agg + (size_t)d * D_LAT;
#pragma unroll
    for (int i = 0; i < 4; i++) {
        float4 v = hs[lane + 32 * i];
        int base = (lane + 32 * i) * 4;
        atomicAdd(ag + base + 0, v.x * w);
        atomicAdd(ag + base + 1, v.y * w);
        atomicAdd(ag + base + 2, v.z * w);
        atomicAdd(ag + base + 3, v.w * w);
    }
}

// ---------------------------------------------------------------------------
// Fused (dual-A) SGEMM:  C = [relu]( A*B (+ agg*B2) + bias )
// 128x128 tile, BK=8, 256 threads, 8x8 microtile.
// A:  selA  < 0 -> extA (harness ptr), else g_h[selA]
// A2: useAgg    -> g_agg
// C:  selC  < 0 -> extC (harness ptr, d_out), else g_h[selC]
// ---------------------------------------------------------------------------
__global__ __launch_bounds__(256) void sgemm_kernel(
    int selA, const float* __restrict__ extA,
    const float* __restrict__ B,
    int useAgg, const float* __restrict__ B2,
    const float* __restrict__ bias,
    int selC, float* __restrict__ extC,
    int M, int N, int K, int doRelu)
{
    __shared__ float As[8][128];
    __shared__ float Bs[8][128];

    const float* A  = (selA < 0) ? extA : g_h[selA];
    float*       C  = (selC < 0) ? extC : g_h[selC];

    const int tid = threadIdx.x;
    const int m0 = blockIdx.y * 128;
    const int n0 = blockIdx.x * 128;

    const int arow = tid >> 1;          // 0..127
    const int acol = (tid & 1) * 4;     // 0 or 4
    const int brow = tid >> 5;          // 0..7
    const int bcol = (tid & 31) * 4;    // 0..124
    const int ty = tid >> 4;            // 0..15
    const int tx = tid & 15;            // 0..15

    float acc[8][8];
#pragma unroll
    for (int i = 0; i < 8; i++)
#pragma unroll
        for (int j = 0; j < 8; j++) acc[i][j] = 0.0f;

    const int npass = useAgg ? 2 : 1;
    for (int pass = 0; pass < npass; pass++) {
        const float* Ap = pass ? (const float*)g_agg : A;
        const float* Bp = pass ? B2 : B;

        for (int k0 = 0; k0 < K; k0 += 8) {
            float4 av = make_float4(0.f, 0.f, 0.f, 0.f);
            if (m0 + arow < M)
                av = *(const float4*)&Ap[(size_t)(m0 + arow) * K + k0 + acol];
            float4 bv = *(const float4*)&Bp[(size_t)(k0 + brow) * N + n0 + bcol];

            __syncthreads();
            As[acol + 0][arow] = av.x;
            As[acol + 1][arow] = av.y;
            As[acol + 2][arow] = av.z;
            As[acol + 3][arow] = av.w;
            *(float4*)&Bs[brow][bcol] = bv;
            __syncthreads();

#pragma unroll
            for (int kk = 0; kk < 8; kk++) {
                float a[8], b[8];
                *(float4*)&a[0] = *(const float4*)&As[kk][ty * 8 + 0];
                *(float4*)&a[4] = *(const float4*)&As[kk][ty * 8 + 4];
                *(float4*)&b[0] = *(const float4*)&Bs[kk][tx * 8 + 0];
                *(float4*)&b[4] = *(const float4*)&Bs[kk][tx * 8 + 4];
#pragma unroll
                for (int i = 0; i < 8; i++)
#pragma unroll
                    for (int j = 0; j < 8; j++)
                        acc[i][j] += a[i] * b[j];
            }
        }
    }

    // Epilogue: bias (+relu), guarded float4 stores
#pragma unroll
    for (int i = 0; i < 8; i++) {
        int m = m0 + ty * 8 + i;
        if (m >= M) continue;
#pragma unroll
        for (int j = 0; j < 8; j += 4) {
            int n = n0 + tx * 8 + j;
            float4 v;
            v.x = acc[i][j + 0] + bias[n + 0];
            v.y = acc[i][j + 1] + bias[n + 1];
            v.z = acc[i][j + 2] + bias[n + 2];
            v.w = acc[i][j + 3] + bias[n + 3];
            if (doRelu) {
                v.x = fmaxf(v.x, 0.f); v.y = fmaxf(v.y, 0.f);
                v.z = fmaxf(v.z, 0.f); v.w = fmaxf(v.w, 0.f);
            }
            *(float4*)&C[(size_t)m * N + n] = v;
        }
    }
}

// ---------------------------------------------------------------------------
// Launch: kernel launches ONLY — no runtime API calls of any kind.
// Inputs (metadata order): features, edge_list, W_enc, b_enc,
//                          W_self[L], W_neigh[L], b_comb[L], W_out, b_out
// ---------------------------------------------------------------------------
extern "C" void kernel_launch(void* const* d_in, const int* in_sizes, int n_in,
                              void* d_out, int out_size) {
    const float* features = (const float*)d_in[0];
    const void*  edges    = d_in[1];
    const float* W_enc    = (const float*)d_in[2];
    const float* b_enc    = (const float*)d_in[3];
    const float* W_self   = (const float*)d_in[4];
    const float* W_neigh  = (const float*)d_in[5];
    const float* b_comb   = (const float*)d_in[6];
    const float* W_out    = (const float*)d_in[7];
    const float* b_out    = (const float*)d_in[8];
    float*       out      = (float*)d_out;

    // Edge dtype detection + degree + per-edge normalization
    detect_kernel<<<1, 32>>>((const int*)edges);
    zero_deg_kernel<<<(N_NODES + 255) / 256, 256>>>();
    deg_kernel<<<(N_EDGES + 255) / 256, 256>>>(edges);
    edgeprep_kernel<<<(N_EDGES + 255) / 256, 256>>>(edges);

    // Encoder: h[0] = features @ W_enc + b_enc
    dim3 gLat(D_LAT / 128, (N_NODES + 127) / 128);
    sgemm_kernel<<<gLat, 256>>>(-1, features, W_enc, 0, nullptr,
                                b_enc, 0, nullptr,
                                N_NODES, D_LAT, D_IN, 0);

    int cur = 0;
    for (int l = 0; l < L_LAYERS; l++) {
        zero_agg_kernel<<<1024, 256>>>();
        scatter_kernel<<<(N_EDGES * 32 + 255) / 256, 256>>>(cur);
        // h[nxt] = relu(h[cur] @ W_self[l] + agg @ W_neigh[l] + b_comb[l])
        sgemm_kernel<<<gLat, 256>>>(cur, nullptr,
                                    W_self + (size_t)l * D_LAT * D_LAT,
                                    1,
                                    W_neigh + (size_t)l * D_LAT * D_LAT,
                                    b_comb + (size_t)l * D_LAT,
                                    1 - cur, nullptr,
                                    N_NODES, D_LAT, D_LAT, 1);
        cur = 1 - cur;
    }

    // Output: out = h[cur] @ W_out + b_out
    dim3 gOut(D_OUT / 128, (N_NODES + 127) / 128);
    sgemm_kernel<<<gOut, 256>>>(cur, nullptr, W_out, 0, nullptr,
                                b_out, -1, out,
                                N_NODES, D_OUT, D_LAT, 0);
}

// round 6
// speedup vs baseline: 2.7576x; 2.7576x over previous
#include <cuda_runtime.h>
#include <cuda_bf16.h>
#include <cstdint>
#include <cstddef>

#define N_NODES 20000
#define N_EDGES 160000
#define D_IN    512
#define D_LAT   512
#define D_OUT   256
#define L_LAYERS 3
#define ROW_U4  (D_LAT / 8)      // 64 uint4 per 512-bf16 row
#define WSZ     (D_LAT * D_LAT)  // 262144

// ---------------------------------------------------------------------------
// Scratch statics — never passed as kernel parameters (device code references
// them directly; selection via int selectors). kernel_launch is launches-only.
// Activations exist ONLY as bf16 (hi, lo) pairs: x == hi + lo to ~2^-17.
// ---------------------------------------------------------------------------
__device__ uint4 g_hhi[2][(size_t)N_NODES * ROW_U4];
__device__ uint4 g_hlo[2][(size_t)N_NODES * ROW_U4];
__device__ uint4 g_agghi[(size_t)N_NODES * ROW_U4];
__device__ uint4 g_agglo[(size_t)N_NODES * ROW_U4];
__device__ uint4 g_fhi[(size_t)N_NODES * ROW_U4];
__device__ uint4 g_flo[(size_t)N_NODES * ROW_U4];
// Transposed split weights, [N][K] layout. enc | self0..2 | neigh0..2 | out
__device__ __nv_bfloat16 g_whi[7 * WSZ + D_LAT * D_OUT];
__device__ __nv_bfloat16 g_wlo[7 * WSZ + D_LAT * D_OUT];
__device__ int    g_degi[N_NODES];
__device__ int    g_off[N_NODES + 1];
__device__ int    g_bsum[128];
__device__ int    g_cursor[N_NODES];
__device__ float2 g_csr[N_EDGES];          // {src_bits, inv_norm}
__device__ int    g_el64;

#define OFF_ENC      0
#define OFF_SELF(l)  ((1 + (l)) * WSZ)
#define OFF_NEIGH(l) ((4 + (l)) * WSZ)
#define OFF_OUT      (7 * WSZ)

// ---------------------------------------------------------------------------
// Small helpers
// ---------------------------------------------------------------------------
__device__ __forceinline__ float2 bf2f(uint32_t u) {
    __nv_bfloat162 b = *(__nv_bfloat162*)&u;
    return __bfloat1622float2(b);
}
__device__ __forceinline__ void split2(float x, float y, uint32_t& hi, uint32_t& lo) {
    __nv_bfloat162 hb = __floats2bfloat162_rn(x, y);
    float2 hf = __bfloat1622float2(hb);
    __nv_bfloat162 lb = __floats2bfloat162_rn(x - hf.x, y - hf.y);
    hi = *(uint32_t*)&hb;
    lo = *(uint32_t*)&lb;
}

// ---------------------------------------------------------------------------
// Edge dtype detection (int64 per reference vs int32 per JAX default-x64-off).
// int64 indices < 20000 -> every odd 32-bit word zero.
// ---------------------------------------------------------------------------
__global__ void detect_kernel(const int* __restrict__ el32) {
    if (threadIdx.x == 0) {
        int any = 0;
        for (int i = 0; i < 256; i++) any |= el32[2 * i + 1];
        g_el64 = (any == 0) ? 1 : 0;
    }
}

__device__ __forceinline__ void load_edge(const void* __restrict__ el,
                                          int e, int& s, int& d) {
    if (g_el64) {
        const long long* p = (const long long*)el;
        s = (int)p[2 * e + 0];
        d = (int)p[2 * e + 1];
    } else {
        const int* p = (const int*)el;
        s = p[2 * e + 0];
        d = p[2 * e + 1];
    }
}

// ---------------------------------------------------------------------------
// CSR build: degree -> blocked exclusive scan -> cursor fill
// ---------------------------------------------------------------------------
__global__ void zero_degi_kernel() {
    int i = blockIdx.x * blockDim.x + threadIdx.x;
    if (i < N_NODES) g_degi[i] = 0;
}

__global__ void degi_kernel(const void* __restrict__ el) {
    int e = blockIdx.x * blockDim.x + threadIdx.x;
    if (e < N_EDGES) {
        int s, d;
        load_edge(el, e, s, d);
        atomicAdd(&g_degi[d], 1);
    }
}

__global__ void scan1_kernel() {   // per-block inclusive scan of counts
    __shared__ int sm[256];
    int tid = threadIdx.x;
    int i = blockIdx.x * 256 + tid;
    int v = (i < N_NODES) ? g_degi[i] : 0;
    sm[tid] = v;
    __syncthreads();
    for (int o = 1; o < 256; o <<= 1) {
        int x = (tid >= o) ? sm[tid - o] : 0;
        __syncthreads();
        sm[tid] += x;
        __syncthreads();
    }
    if (i < N_NODES) g_off[i] = sm[tid] - v;   // exclusive within block
    if (tid == 255) g_bsum[blockIdx.x] = sm[255];
}

__global__ void scan2_kernel(int nblocks) {    // serial scan of block sums
    if (threadIdx.x == 0 && blockIdx.x == 0) {
        int run = 0;
        for (int b = 0; b < nblocks; b++) {
            int t = g_bsum[b];
            g_bsum[b] = run;
            run += t;
        }
    }
}

__global__ void scan3_kernel() {
    int i = blockIdx.x * blockDim.x + threadIdx.x;
    if (i < N_NODES) {
        int o = g_off[i] + g_bsum[i >> 8];
        g_off[i] = o;
        g_cursor[i] = o;
    }
    if (i == 0) g_off[N_NODES] = N_EDGES;
}

__global__ void fill_kernel(const void* __restrict__ el) {
    int e = blockIdx.x * blockDim.x + threadIdx.x;
    if (e < N_EDGES) {
        int s, d;
        load_edge(el, e, s, d);
        float w = rsqrtf((float)(g_degi[d] + 1) * (float)(g_degi[s] + 1));
        int pos = atomicAdd(&g_cursor[d], 1);
        g_csr[pos] = make_float2(__int_as_float(s), w);
    }
}

// ---------------------------------------------------------------------------
// Split features fp32 -> (hi, lo) bf16 pairs
// ---------------------------------------------------------------------------
__global__ void fsplit_kernel(const float* __restrict__ f) {
    int i = blockIdx.x * blockDim.x + threadIdx.x;  // u32-pair index
    const int n = N_NODES * D_IN / 2;
    if (i < n) {
        float2 v = ((const float2*)f)[i];
        uint32_t hi, lo;
        split2(v.x, v.y, hi, lo);
        ((uint32_t*)g_fhi)[i] = hi;
        ((uint32_t*)g_flo)[i] = lo;
    }
}

// ---------------------------------------------------------------------------
// Weight prep: src fp32 [K][N] -> transposed split bf16 [N][K] at dstOff.
// Tiled 32x32 transpose. K, N multiples of 32.
// ---------------------------------------------------------------------------
__global__ void wprep_kernel(const float* __restrict__ src, int dstOff,
                             int K, int N) {
    __shared__ float t[32][33];
    int tx = threadIdx.x, ty = threadIdx.y;   // block (32, 8)
    int n0 = blockIdx.x * 32, k0 = blockIdx.y * 32;
#pragma unroll
    for (int j = 0; j < 4; j++)
        t[ty + j * 8][tx] = src[(size_t)(k0 + ty + j * 8) * N + n0 + tx];
    __syncthreads();
#pragma unroll
    for (int j = 0; j < 4; j++) {
        int n = n0 + ty + j * 8;
        int k = k0 + tx;
        float v = t[tx][ty + j * 8];
        __nv_bfloat16 hi = __float2bfloat16_rn(v);
        __nv_bfloat16 lo = __float2bfloat16_rn(v - __bfloat162float(hi));
        g_whi[(size_t)dstOff + (size_t)n * K + k] = hi;
        g_wlo[(size_t)dstOff + (size_t)n * K + k] = lo;
    }
}

// ---------------------------------------------------------------------------
// Gather (replaces atomic scatter): one warp per dst node.
// agg[d] = sum_{e in CSR[d]} w_e * (hhi+hlo)[src_e]; written as split pair.
// ---------------------------------------------------------------------------
__global__ __launch_bounds__(256) void gather_kernel(int hsel) {
    int gw = (blockIdx.x * blockDim.x + threadIdx.x) >> 5;
    int lane = threadIdx.x & 31;
    if (gw >= N_NODES) return;
    int beg = g_off[gw], end = g_off[gw + 1];

    float acc[16];
#pragma unroll
    for (int i = 0; i < 16; i++) acc[i] = 0.0f;

    const uint4* Hh = g_hhi[hsel];
    const uint4* Hl = g_hlo[hsel];
    for (int i = beg; i < end; i++) {
        float2 er = g_csr[i];
        int s = __float_as_int(er.x);
        float w = er.y;
        const uint4* rh = Hh + (size_t)s * ROW_U4;
        const uint4* rl = Hl + (size_t)s * ROW_U4;
#pragma unroll
        for (int j = 0; j < 2; j++) {
            uint4 hv = rh[lane + 32 * j];
            uint4 lv = rl[lane + 32 * j];
            float2 a, b;
            a = bf2f(hv.x); b = bf2f(lv.x);
            acc[j * 8 + 0] += w * (a.x + b.x); acc[j * 8 + 1] += w * (a.y + b.y);
            a = bf2f(hv.y); b = bf2f(lv.y);
            acc[j * 8 + 2] += w * (a.x + b.x); acc[j * 8 + 3] += w * (a.y + b.y);
            a = bf2f(hv.z); b = bf2f(lv.z);
            acc[j * 8 + 4] += w * (a.x + b.x); acc[j * 8 + 5] += w * (a.y + b.y);
            a = bf2f(hv.w); b = bf2f(lv.w);
            acc[j * 8 + 6] += w * (a.x + b.x); acc[j * 8 + 7] += w * (a.y + b.y);
        }
    }
#pragma unroll
    for (int j = 0; j < 2; j++) {
        uint32_t ph[4], pl[4];
#pragma unroll
        for (int k = 0; k < 4; k++)
            split2(acc[j * 8 + k * 2], acc[j * 8 + k * 2 + 1], ph[k], pl[k]);
        g_agghi[(size_t)gw * ROW_U4 + lane + 32 * j] = make_uint4(ph[0], ph[1], ph[2], ph[3]);
        g_agglo[(size_t)gw * ROW_U4 + lane + 32 * j] = make_uint4(pl[0], pl[1], pl[2], pl[3]);
    }
}

// ---------------------------------------------------------------------------
// Tensor-core GEMM, bf16 split-3:  C = [relu]( A*W (+ Agg*W2) + bias )
//   A given as (hi, lo) bf16 pairs [M][K]; W as transposed pairs [N][K].
//   C = Ahi*Whi + Ahi*Wlo + Alo*Whi  (error ~ eps_bf16^2).
// 128x128 tile, BK=16, 256 threads (8 warps of 64x32), cp.async double buffer.
// aSel: 0/1 -> g_h pair, 2 -> features pair. cSel: 0/1 -> write g_h pair,
// -1 -> fp32 extC.  useAgg: second accumulation pass A=g_agg pair, W at wOff2.
// ---------------------------------------------------------------------------
__device__ __forceinline__ void cp16(uint32_t d, const void* s, int sz) {
    asm volatile("cp.async.cg.shared.global [%0], [%1], 16, %2;\n"
                 :: "r"(d), "l"(s), "r"(sz));
}
#define CP_COMMIT() asm volatile("cp.async.commit_group;\n")
#define CP_WAIT1()  asm volatile("cp.async.wait_group 1;\n")
#define CP_WAIT0()  asm volatile("cp.async.wait_group 0;\n")

#define MMA_BF16(d, a, b)                                                     \
    asm volatile(                                                             \
        "mma.sync.aligned.m16n8k16.row.col.f32.bf16.bf16.f32 "                \
        "{%0,%1,%2,%3}, {%4,%5,%6,%7}, {%8,%9}, {%0,%1,%2,%3};\n"             \
        : "+f"(d[0]), "+f"(d[1]), "+f"(d[2]), "+f"(d[3])                      \
        : "r"(a[0]), "r"(a[1]), "r"(a[2]), "r"(a[3]), "r"(b[0]), "r"(b[1]))

__global__ __launch_bounds__(256) void gemm_kernel(
    int aSel, int wOff, int useAgg, int wOff2,
    const float* __restrict__ bias,
    int cSel, float* __restrict__ extC,
    int M, int N, int K, int doRelu)
{
    // [2 buffers][128 rows][8 u32 (16 bf16)]
    __shared__ uint32_t sAh[2][128 * 8], sAl[2][128 * 8];
    __shared__ uint32_t sBh[2][128 * 8], sBl[2][128 * 8];

    const int tid = threadIdx.x;
    const int wid = tid >> 5, lane = tid & 31;
    const int wm = (wid >> 2) * 64, wn = (wid & 3) * 32;
    const int m0 = blockIdx.y * 128, n0 = blockIdx.x * 128;
    const int g = lane >> 2, c = lane & 3;

    float acc[4][4][4];
#pragma unroll
    for (int a = 0; a < 4; a++)
#pragma unroll
        for (int b = 0; b < 4; b++)
#pragma unroll
            for (int d = 0; d < 4; d++) acc[a][b][d] = 0.0f;

    const int lr = tid >> 1, seg = tid & 1;         // loader: row, 16B segment
    const int arow = m0 + lr;
    const int avalid = (arow < M) ? 16 : 0;
    const int ar = (arow < M) ? arow : (M - 1);
    const uint32_t swst = ((uint32_t)(seg * 16)) ^ ((((uint32_t)lr >> 2) & 1) << 4);
    const uint32_t dA = (uint32_t)(lr * 32) + swst;

    const int npass = useAgg ? 2 : 1;
    for (int pass = 0; pass < npass; pass++) {
        const __nv_bfloat16 *pAh, *pAl, *pBh, *pBl;
        if (pass == 0) {
            pAh = (aSel == 2) ? (const __nv_bfloat16*)g_fhi
                              : (const __nv_bfloat16*)g_hhi[aSel];
            pAl = (aSel == 2) ? (const __nv_bfloat16*)g_flo
                              : (const __nv_bfloat16*)g_hlo[aSel];
            pBh = g_whi + wOff;
            pBl = g_wlo + wOff;
        } else {
            pAh = (const __nv_bfloat16*)g_agghi;
            pAl = (const __nv_bfloat16*)g_agglo;
            pBh = g_whi + wOff2;
            pBl = g_wlo + wOff2;
        }
        const __nv_bfloat16* aH = pAh + (size_t)ar * K + seg * 8;
        const __nv_bfloat16* aL = pAl + (size_t)ar * K + seg * 8;
        const __nv_bfloat16* bH = pBh + (size_t)(n0 + lr) * K + seg * 8;
        const __nv_bfloat16* bL = pBl + (size_t)(n0 + lr) * K + seg * 8;

        uint32_t bAh0 = (uint32_t)__cvta_generic_to_shared(&sAh[0][0]);
        uint32_t bAl0 = (uint32_t)__cvta_generic_to_shared(&sAl[0][0]);
        uint32_t bBh0 = (uint32_t)__cvta_generic_to_shared(&sBh[0][0]);
        uint32_t bBl0 = (uint32_t)__cvta_generic_to_shared(&sBl[0][0]);

        const int NK = K / 16;
        // prologue: stage 0
        cp16(bAh0 + dA, aH, avalid);
        cp16(bAl0 + dA, aL, avalid);
        cp16(bBh0 + dA, bH, 16);
        cp16(bBl0 + dA, bL, 16);
        CP_COMMIT();

        for (int kt = 0; kt < NK; kt++) {
            int buf = kt & 1;
            if (kt + 1 < NK) {
                int nb = (kt + 1) & 1;
                uint32_t o = (uint32_t)(nb * 128 * 8 * 4);
                int kc = (kt + 1) * 16;
                cp16(bAh0 + o + dA, aH + kc, avalid);
                cp16(bAl0 + o + dA, aL + kc, avalid);
                cp16(bBh0 + o + dA, bH + kc, 16);
                cp16(bBl0 + o + dA, bL + kc, 16);
                CP_COMMIT();
                CP_WAIT1();
            } else {
                CP_WAIT0();
            }
            __syncthreads();

            // B fragments (4 n-tiles x 2 regs, hi and lo)
            uint32_t bh[4][2], bl[4][2];
#pragma unroll
            for (int nt = 0; nt < 4; nt++) {
                int row = wn + nt * 8 + g;
                int sw = ((row >> 2) & 1) << 2;
                int base = row * 8;
                bh[nt][0] = sBh[buf][base + (c ^ sw)];
                bh[nt][1] = sBh[buf][base + ((c + 4) ^ sw)];
                bl[nt][0] = sBl[buf][base + (c ^ sw)];
                bl[nt][1] = sBl[buf][base + ((c + 4) ^ sw)];
            }
            // A fragments (4 m-tiles x 4 regs, hi and lo) + MMAs
#pragma unroll
            for (int mt = 0; mt < 4; mt++) {
                int r0 = wm + mt * 16 + g;
                int r1 = r0 + 8;
                int sw0 = ((r0 >> 2) & 1) << 2;
                int sw1 = ((r1 >> 2) & 1) << 2;
                uint32_t ah[4], al[4];
                ah[0] = sAh[buf][r0 * 8 + (c ^ sw0)];
                ah[1] = sAh[buf][r1 * 8 + (c ^ sw1)];
                ah[2] = sAh[buf][r0 * 8 + ((c + 4) ^ sw0)];
                ah[3] = sAh[buf][r1 * 8 + ((c + 4) ^ sw1)];
                al[0] = sAl[buf][r0 * 8 + (c ^ sw0)];
                al[1] = sAl[buf][r1 * 8 + (c ^ sw1)];
                al[2] = sAl[buf][r0 * 8 + ((c + 4) ^ sw0)];
                al[3] = sAl[buf][r1 * 8 + ((c + 4) ^ sw1)];
#pragma unroll
                for (int nt = 0; nt < 4; nt++) {
                    MMA_BF16(acc[mt][nt], ah, bh[nt]);
                    MMA_BF16(acc[mt][nt], ah, bl[nt]);
                    MMA_BF16(acc[mt][nt], al, bh[nt]);
                }
            }
            __syncthreads();
        }
    }

    // Epilogue
#pragma unroll
    for (int mt = 0; mt < 4; mt++) {
#pragma unroll
        for (int nt = 0; nt < 4; nt++) {
            int gn = n0 + wn + nt * 8 + 2 * c;
            float b0 = bias[gn], b1 = bias[gn + 1];
#pragma unroll
            for (int half = 0; half < 2; half++) {
                int grow = m0 + wm + mt * 16 + g + half * 8;
                if (grow >= M) continue;
                float v0 = acc[mt][nt][half * 2 + 0] + b0;
                float v1 = acc[mt][nt][half * 2 + 1] + b1;
                if (doRelu) { v0 = fmaxf(v0, 0.f); v1 = fmaxf(v1, 0.f); }
                if (cSel >= 0) {
                    uint32_t hi, lo;
                    split2(v0, v1, hi, lo);
                    size_t idx = (size_t)grow * (D_LAT / 2) + (gn >> 1);
                    ((uint32_t*)g_hhi[cSel])[idx] = hi;
                    ((uint32_t*)g_hlo[cSel])[idx] = lo;
                } else {
                    *(float2*)&extC[(size_t)grow * N + gn] = make_float2(v0, v1);
                }
            }
        }
    }
}

// ---------------------------------------------------------------------------
// Launch: kernel launches ONLY.
// Inputs: features, edge_list, W_enc, b_enc, W_self[L], W_neigh[L],
//         b_comb[L], W_out, b_out
// ---------------------------------------------------------------------------
extern "C" void kernel_launch(void* const* d_in, const int* in_sizes, int n_in,
                              void* d_out, int out_size) {
    const float* features = (const float*)d_in[0];
    const void*  edges    = d_in[1];
    const float* W_enc    = (const float*)d_in[2];
    const float* b_enc    = (const float*)d_in[3];
    const float* W_self   = (const float*)d_in[4];
    const float* W_neigh  = (const float*)d_in[5];
    const float* b_comb   = (const float*)d_in[6];
    const float* W_out    = (const float*)d_in[7];
    const float* b_out    = (const float*)d_in[8];
    float*       out      = (float*)d_out;

    const int SCAN_BLOCKS = (N_NODES + 255) / 256;  // 79

    // Edge dtype + CSR build
    detect_kernel<<<1, 32>>>((const int*)edges);
    zero_degi_kernel<<<SCAN_BLOCKS, 256>>>();
    degi_kernel<<<(N_EDGES + 255) / 256, 256>>>(edges);
    scan1_kernel<<<SCAN_BLOCKS, 256>>>();
    scan2_kernel<<<1, 32>>>(SCAN_BLOCKS);
    scan3_kernel<<<SCAN_BLOCKS, 256>>>();
    fill_kernel<<<(N_EDGES + 255) / 256, 256>>>(edges);

    // Split features; transpose+split weights
    fsplit_kernel<<<(N_NODES * D_IN / 2 + 255) / 256, 256>>>(features);
    dim3 wb(32, 8);
    wprep_kernel<<<dim3(D_LAT / 32, D_IN / 32), wb>>>(W_enc, OFF_ENC, D_IN, D_LAT);
    for (int l = 0; l < L_LAYERS; l++) {
        wprep_kernel<<<dim3(D_LAT / 32, D_LAT / 32), wb>>>(
            W_self + (size_t)l * WSZ, OFF_SELF(l), D_LAT, D_LAT);
        wprep_kernel<<<dim3(D_LAT / 32, D_LAT / 32), wb>>>(
            W_neigh + (size_t)l * WSZ, OFF_NEIGH(l), D_LAT, D_LAT);
    }
    wprep_kernel<<<dim3(D_OUT / 32, D_LAT / 32), wb>>>(W_out, OFF_OUT, D_LAT, D_OUT);

    // Encoder: h[0] = features @ W_enc + b_enc
    dim3 gLat(D_LAT / 128, (N_NODES + 127) / 128);
    gemm_kernel<<<gLat, 256>>>(2, OFF_ENC, 0, 0, b_enc, 0, nullptr,
                               N_NODES, D_LAT, D_IN, 0);

    int cur = 0;
    for (int l = 0; l < L_LAYERS; l++) {
        gather_kernel<<<(N_NODES * 32 + 255) / 256, 256>>>(cur);
        gemm_kernel<<<gLat, 256>>>(cur, OFF_SELF(l), 1, OFF_NEIGH(l),
                                   b_comb + (size_t)l * D_LAT,
                                   1 - cur, nullptr,
                                   N_NODES, D_LAT, D_LAT, 1);
        cur = 1 - cur;
    }

    // Output: out = h[cur] @ W_out + b_out  (fp32)
    dim3 gOut(D_OUT / 128, (N_NODES + 127) / 128);
    gemm_kernel<<<gOut, 256>>>(cur, OFF_OUT, 0, 0, b_out, -1, out,
                               N_NODES, D_OUT, D_LAT, 0);
}

// round 8
// speedup vs baseline: 2.9791x; 1.0803x over previous
#include <cuda_runtime.h>
#include <cuda_bf16.h>
#include <cstdint>
#include <cstddef>

#define N_NODES 20000
#define N_EDGES 160000
#define D_IN    512
#define D_LAT   512
#define D_OUT   256
#define L_LAYERS 3
#define ROW_U4  (D_LAT / 8)
#define WSZ     (D_LAT * D_LAT)

// ---------------------------------------------------------------------------
// Scratch statics. Activations live only as bf16 (hi, lo) pairs.
// ---------------------------------------------------------------------------
__device__ uint4 g_hhi[2][(size_t)N_NODES * ROW_U4];
__device__ uint4 g_hlo[2][(size_t)N_NODES * ROW_U4];
__device__ uint4 g_agghi[(size_t)N_NODES * ROW_U4];
__device__ uint4 g_agglo[(size_t)N_NODES * ROW_U4];
__device__ uint4 g_fhi[(size_t)N_NODES * ROW_U4];
__device__ uint4 g_flo[(size_t)N_NODES * ROW_U4];
__device__ __nv_bfloat16 g_whi[7 * WSZ + D_LAT * D_OUT];
__device__ __nv_bfloat16 g_wlo[7 * WSZ + D_LAT * D_OUT];
__device__ int    g_degi[N_NODES];
__device__ int    g_off[N_NODES + 1];
__device__ int    g_bsum[128];
__device__ int    g_cursor[N_NODES];
__device__ float2 g_csr[N_EDGES];
__device__ int    g_el64;

#define OFF_ENC      0
#define OFF_SELF(l)  ((1 + (l)) * WSZ)
#define OFF_NEIGH(l) ((4 + (l)) * WSZ)
#define OFF_OUT      (7 * WSZ)

__device__ __forceinline__ float2 bf2f(uint32_t u) {
    __nv_bfloat162 b = *(__nv_bfloat162*)&u;
    return __bfloat1622float2(b);
}
__device__ __forceinline__ void split2(float x, float y, uint32_t& hi, uint32_t& lo) {
    __nv_bfloat162 hb = __floats2bfloat162_rn(x, y);
    float2 hf = __bfloat1622float2(hb);
    __nv_bfloat162 lb = __floats2bfloat162_rn(x - hf.x, y - hf.y);
    hi = *(uint32_t*)&hb;
    lo = *(uint32_t*)&lb;
}

// ---------------------------------------------------------------------------
// Edge dtype detection (int64 per reference vs int32 per JAX x64-off)
// ---------------------------------------------------------------------------
__global__ void detect_kernel(const int* __restrict__ el32) {
    if (threadIdx.x == 0) {
        int any = 0;
        for (int i = 0; i < 256; i++) any |= el32[2 * i + 1];
        g_el64 = (any == 0) ? 1 : 0;
    }
}

__device__ __forceinline__ void load_edge(const void* __restrict__ el,
                                          int e, int& s, int& d) {
    if (g_el64) {
        const long long* p = (const long long*)el;
        s = (int)p[2 * e + 0];
        d = (int)p[2 * e + 1];
    } else {
        const int* p = (const int*)el;
        s = p[2 * e + 0];
        d = p[2 * e + 1];
    }
}

// ---------------------------------------------------------------------------
// CSR build
// ---------------------------------------------------------------------------
__global__ void zero_degi_kernel() {
    int i = blockIdx.x * blockDim.x + threadIdx.x;
    if (i < N_NODES) g_degi[i] = 0;
}

__global__ void degi_kernel(const void* __restrict__ el) {
    int e = blockIdx.x * blockDim.x + threadIdx.x;
    if (e < N_EDGES) {
        int s, d;
        load_edge(el, e, s, d);
        atomicAdd(&g_degi[d], 1);
    }
}

__global__ void scan1_kernel() {
    __shared__ int sm[256];
    int tid = threadIdx.x;
    int i = blockIdx.x * 256 + tid;
    int v = (i < N_NODES) ? g_degi[i] : 0;
    sm[tid] = v;
    __syncthreads();
    for (int o = 1; o < 256; o <<= 1) {
        int x = (tid >= o) ? sm[tid - o] : 0;
        __syncthreads();
        sm[tid] += x;
        __syncthreads();
    }
    if (i < N_NODES) g_off[i] = sm[tid] - v;
    if (tid == 255) g_bsum[blockIdx.x] = sm[255];
}

__global__ void scan2_kernel(int nblocks) {
    if (threadIdx.x == 0 && blockIdx.x == 0) {
        int run = 0;
        for (int b = 0; b < nblocks; b++) {
            int t = g_bsum[b];
            g_bsum[b] = run;
            run += t;
        }
    }
}

__global__ void scan3_kernel() {
    int i = blockIdx.x * blockDim.x + threadIdx.x;
    if (i < N_NODES) {
        int o = g_off[i] + g_bsum[i >> 8];
        g_off[i] = o;
        g_cursor[i] = o;
    }
    if (i == 0) g_off[N_NODES] = N_EDGES;
}

__global__ void fill_kernel(const void* __restrict__ el) {
    int e = blockIdx.x * blockDim.x + threadIdx.x;
    if (e < N_EDGES) {
        int s, d;
        load_edge(el, e, s, d);
        float w = rsqrtf((float)(g_degi[d] + 1) * (float)(g_degi[s] + 1));
        int pos = atomicAdd(&g_cursor[d], 1);
        g_csr[pos] = make_float2(__int_as_float(s), w);
    }
}

// ---------------------------------------------------------------------------
// Feature split + weight prep (transpose fp32 [K][N] -> split bf16 [N][K])
// ---------------------------------------------------------------------------
__global__ void fsplit_kernel(const float* __restrict__ f) {
    int i = blockIdx.x * blockDim.x + threadIdx.x;
    const int n = N_NODES * D_IN / 2;
    if (i < n) {
        float2 v = ((const float2*)f)[i];
        uint32_t hi, lo;
        split2(v.x, v.y, hi, lo);
        ((uint32_t*)g_fhi)[i] = hi;
        ((uint32_t*)g_flo)[i] = lo;
    }
}

__global__ void wprep_kernel(const float* __restrict__ src, int dstOff,
                             int K, int N) {
    __shared__ float t[32][33];
    int tx = threadIdx.x, ty = threadIdx.y;
    int n0 = blockIdx.x * 32, k0 = blockIdx.y * 32;
#pragma unroll
    for (int j = 0; j < 4; j++)
        t[ty + j * 8][tx] = src[(size_t)(k0 + ty + j * 8) * N + n0 + tx];
    __syncthreads();
#pragma unroll
    for (int j = 0; j < 4; j++) {
        int n = n0 + ty + j * 8;
        int k = k0 + tx;
        float v = t[tx][ty + j * 8];
        __nv_bfloat16 hi = __float2bfloat16_rn(v);
        __nv_bfloat16 lo = __float2bfloat16_rn(v - __bfloat162float(hi));
        g_whi[(size_t)dstOff + (size_t)n * K + k] = hi;
        g_wlo[(size_t)dstOff + (size_t)n * K + k] = lo;
    }
}

// ---------------------------------------------------------------------------
// Gather: one warp per dst node; agg = sum w_e * (hi+lo)[src]
// ---------------------------------------------------------------------------
__global__ __launch_bounds__(256) void gather_kernel(int hsel) {
    int gw = (blockIdx.x * blockDim.x + threadIdx.x) >> 5;
    int lane = threadIdx.x & 31;
    if (gw >= N_NODES) return;
    int beg = g_off[gw], end = g_off[gw + 1];

    float acc[16];
#pragma unroll
    for (int i = 0; i < 16; i++) acc[i] = 0.0f;

    const uint4* Hh = g_hhi[hsel];
    const uint4* Hl = g_hlo[hsel];
    for (int i = beg; i < end; i++) {
        float2 er = g_csr[i];
        int s = __float_as_int(er.x);
        float w = er.y;
        const uint4* rh = Hh + (size_t)s * ROW_U4;
        const uint4* rl = Hl + (size_t)s * ROW_U4;
#pragma unroll
        for (int j = 0; j < 2; j++) {
            uint4 hv = rh[lane + 32 * j];
            uint4 lv = rl[lane + 32 * j];
            float2 a, b;
            a = bf2f(hv.x); b = bf2f(lv.x);
            acc[j * 8 + 0] += w * (a.x + b.x); acc[j * 8 + 1] += w * (a.y + b.y);
            a = bf2f(hv.y); b = bf2f(lv.y);
            acc[j * 8 + 2] += w * (a.x + b.x); acc[j * 8 + 3] += w * (a.y + b.y);
            a = bf2f(hv.z); b = bf2f(lv.z);
            acc[j * 8 + 4] += w * (a.x + b.x); acc[j * 8 + 5] += w * (a.y + b.y);
            a = bf2f(hv.w); b = bf2f(lv.w);
            acc[j * 8 + 6] += w * (a.x + b.x); acc[j * 8 + 7] += w * (a.y + b.y);
        }
    }
#pragma unroll
    for (int j = 0; j < 2; j++) {
        uint32_t ph[4], pl[4];
#pragma unroll
        for (int k = 0; k < 4; k++)
            split2(acc[j * 8 + k * 2], acc[j * 8 + k * 2 + 1], ph[k], pl[k]);
        g_agghi[(size_t)gw * ROW_U4 + lane + 32 * j] = make_uint4(ph[0], ph[1], ph[2], ph[3]);
        g_agglo[(size_t)gw * ROW_U4 + lane + 32 * j] = make_uint4(pl[0], pl[1], pl[2], pl[3]);
    }
}

// ---------------------------------------------------------------------------
// mma.sync GEMM, bf16 split-3:  C = [relu]( A*W (+ Agg*W2) + bias )
// 128x128 tile, BK=32 (2 k16 subs), 2-stage cp.async, ldmatrix fragments.
// Tiles in smem: [stage][4 tiles: Ah Al Bh Bl][2 subs][128 rows][32B], XOR
// swizzled (seg ^ row-bit2) -> conflict-free ldmatrix.
// ---------------------------------------------------------------------------
#define GEMM_SMEM 65536
#define TS(s, t) ((uint32_t)(s) * 32768u + (uint32_t)(t) * 8192u)

__device__ __forceinline__ void cp16(uint32_t d, const void* s, int sz) {
    asm volatile("cp.async.cg.shared.global [%0], [%1], 16, %2;\n"
                 :: "r"(d), "l"(s), "r"(sz));
}

#define LDM4(r, addr)                                                         \
    asm volatile("ldmatrix.sync.aligned.m8n8.x4.shared.b16 "                  \
                 "{%0, %1, %2, %3}, [%4];"                                    \
                 : "=r"((r)[0]), "=r"((r)[1]), "=r"((r)[2]), "=r"((r)[3])     \
                 : "r"(addr))

#define MMA4(d, a, b0v, b1v)                                                  \
    asm volatile(                                                             \
        "mma.sync.aligned.m16n8k16.row.col.f32.bf16.bf16.f32 "                \
        "{%0,%1,%2,%3}, {%4,%5,%6,%7}, {%8,%9}, {%0,%1,%2,%3};\n"             \
        : "+f"((d)[0]), "+f"((d)[1]), "+f"((d)[2]), "+f"((d)[3])              \
        : "r"((a)[0]), "r"((a)[1]), "r"((a)[2]), "r"((a)[3]),                 \
          "r"(b0v), "r"(b1v))

__global__ __launch_bounds__(256, 2) void gemm_kernel(
    int aSel, int wOff, int useAgg, int wOff2,
    const float* __restrict__ bias,
    int cSel, float* __restrict__ extC,
    int M, int Ntot, int doRelu)
{
    extern __shared__ char smem[];
    uint32_t sb = (uint32_t)__cvta_generic_to_shared(smem);
    const int tid = threadIdx.x;
    const int wid = tid >> 5, lane = tid & 31;
    const int wm = (wid >> 2) * 64, wn = (wid & 3) * 32;
    const int m0 = blockIdx.y * 128, n0 = blockIdx.x * 128;
    const int li = lane & 7, quad = lane >> 3;

    float acc[4][4][4];
#pragma unroll
    for (int a = 0; a < 4; a++)
#pragma unroll
        for (int b = 0; b < 4; b++)
#pragma unroll
            for (int d = 0; d < 4; d++) acc[a][b][d] = 0.0f;

    // Lane-fixed fragment offsets (within a sub-tile).
    // A (m16k16): quads -> (a0: m0-7 k0-7)(a1: m8-15 k0-7)(a2: m0-7 k8-15)(a3: m8-15 k8-15)
    const int rA = (quad & 1) * 8 + li;
    const int sgA = quad >> 1;
    // B pair (n16k16): (b0 ntEven)(b1 ntEven)(b0 ntOdd)(b1 ntOdd)
    const int rB = (quad >> 1) * 8 + li;
    const int sgB = quad & 1;

    uint32_t offA[4], offB[2];
#pragma unroll
    for (int mt = 0; mt < 4; mt++) {
        int row = wm + mt * 16 + rA;
        offA[mt] = (uint32_t)(row * 32 + ((sgA ^ ((row >> 2) & 1)) * 16));
    }
#pragma unroll
    for (int ntp = 0; ntp < 2; ntp++) {
        int row = wn + ntp * 16 + rB;
        offB[ntp] = (uint32_t)(row * 32 + ((sgB ^ ((row >> 2) & 1)) * 16));
    }

    auto load_chunk = [&](int chunk, int stage) {
        const __nv_bfloat16 *Ah, *Al, *Bh, *Bl;
        if (chunk < 16) {
            Ah = (aSel == 2) ? (const __nv_bfloat16*)g_fhi
                             : (const __nv_bfloat16*)g_hhi[aSel];
            Al = (aSel == 2) ? (const __nv_bfloat16*)g_flo
                             : (const __nv_bfloat16*)g_hlo[aSel];
            Bh = g_whi + wOff;
            Bl = g_wlo + wOff;
        } else {
            Ah = (const __nv_bfloat16*)g_agghi;
            Al = (const __nv_bfloat16*)g_agglo;
            Bh = g_whi + wOff2;
            Bl = g_wlo + wOff2;
        }
        const int kk = (chunk & 15) * 32;
#pragma unroll
        for (int t = 0; t < 4; t++) {
            const __nv_bfloat16* src = (t == 0) ? Ah : (t == 1) ? Al
                                     : (t == 2) ? Bh : Bl;
            const bool isA = (t < 2);
#pragma unroll
            for (int i = 0; i < 2; i++) {
                int idx = tid + i * 256;          // 0..511
                int row = idx >> 2;
                int sub = (idx >> 1) & 1;
                int seg = idx & 1;
                int grow, valid;
                if (isA) {
                    int am = m0 + row;
                    valid = (am < M) ? 16 : 0;
                    grow = (am < M) ? am : 0;
                } else {
                    valid = 16;
                    grow = n0 + row;
                }
                const char* p = (const char*)(src + (size_t)grow * 512
                                              + kk + sub * 16 + seg * 8);
                uint32_t so = sb + TS(stage, t)
                            + (uint32_t)(sub * 4096 + row * 32
                                         + ((seg ^ ((row >> 2) & 1)) * 16));
                cp16(so, p, valid);
            }
        }
        asm volatile("cp.async.commit_group;\n");
    };

    const int NC = useAgg ? 32 : 16;
    load_chunk(0, 0);

    for (int kt = 0; kt < NC; kt++) {
        int s = kt & 1;
        if (kt + 1 < NC) {
            load_chunk(kt + 1, s ^ 1);
            asm volatile("cp.async.wait_group 1;\n");
        } else {
            asm volatile("cp.async.wait_group 0;\n");
        }
        __syncthreads();

#pragma unroll
        for (int sub = 0; sub < 2; sub++) {
            uint32_t so = (uint32_t)(sub * 4096);
            uint32_t bh[2][4], bl[2][4];
#pragma unroll
            for (int ntp = 0; ntp < 2; ntp++) {
                LDM4(bh[ntp], sb + TS(s, 2) + so + offB[ntp]);
                LDM4(bl[ntp], sb + TS(s, 3) + so + offB[ntp]);
            }
#pragma unroll
            for (int mt = 0; mt < 4; mt++) {
                uint32_t ah[4], al[4];
                LDM4(ah, sb + TS(s, 0) + so + offA[mt]);
                LDM4(al, sb + TS(s, 1) + so + offA[mt]);
#pragma unroll
                for (int nt = 0; nt < 4; nt++) {
                    int ntp = nt >> 1, o = (nt & 1) * 2;
                    MMA4(acc[mt][nt], ah, bh[ntp][o], bh[ntp][o + 1]);
                    MMA4(acc[mt][nt], ah, bl[ntp][o], bl[ntp][o + 1]);
                    MMA4(acc[mt][nt], al, bh[ntp][o], bh[ntp][o + 1]);
                }
            }
        }
        __syncthreads();
    }

    // Epilogue
    const int g = lane >> 2, c = lane & 3;
#pragma unroll
    for (int mt = 0; mt < 4; mt++) {
#pragma unroll
        for (int nt = 0; nt < 4; nt++) {
            int gn = n0 + wn + nt * 8 + 2 * c;
            float b0 = bias[gn], b1 = bias[gn + 1];
#pragma unroll
            for (int half = 0; half < 2; half++) {
                int grow = m0 + wm + mt * 16 + g + half * 8;
                if (grow >= M) continue;
                float v0 = acc[mt][nt][half * 2 + 0] + b0;
                float v1 = acc[mt][nt][half * 2 + 1] + b1;
                if (doRelu) { v0 = fmaxf(v0, 0.f); v1 = fmaxf(v1, 0.f); }
                if (cSel >= 0) {
                    uint32_t hi, lo;
                    split2(v0, v1, hi, lo);
                    size_t idx = (size_t)grow * (D_LAT / 2) + (gn >> 1);
                    ((uint32_t*)g_hhi[cSel])[idx] = hi;
                    ((uint32_t*)g_hlo[cSel])[idx] = lo;
                } else {
                    *(float2*)&extC[(size_t)grow * Ntot + gn] = make_float2(v0, v1);
                }
            }
        }
    }
}

// ---------------------------------------------------------------------------
// Launch
// ---------------------------------------------------------------------------
extern "C" void kernel_launch(void* const* d_in, const int* in_sizes, int n_in,
                              void* d_out, int out_size) {
    const float* features = (const float*)d_in[0];
    const void*  edges    = d_in[1];
    const float* W_enc    = (const float*)d_in[2];
    const float* b_enc    = (const float*)d_in[3];
    const float* W_self   = (const float*)d_in[4];
    const float* W_neigh  = (const float*)d_in[5];
    const float* b_comb   = (const float*)d_in[6];
    const float* W_out    = (const float*)d_in[7];
    const float* b_out    = (const float*)d_in[8];
    float*       out      = (float*)d_out;

    cudaFuncSetAttribute(gemm_kernel,
                         cudaFuncAttributeMaxDynamicSharedMemorySize, GEMM_SMEM);

    const int SCAN_BLOCKS = (N_NODES + 255) / 256;

    detect_kernel<<<1, 32>>>((const int*)edges);
    zero_degi_kernel<<<SCAN_BLOCKS, 256>>>();
    degi_kernel<<<(N_EDGES + 255) / 256, 256>>>(edges);
    scan1_kernel<<<SCAN_BLOCKS, 256>>>();
    scan2_kernel<<<1, 32>>>(SCAN_BLOCKS);
    scan3_kernel<<<SCAN_BLOCKS, 256>>>();
    fill_kernel<<<(N_EDGES + 255) / 256, 256>>>(edges);

    fsplit_kernel<<<(N_NODES * D_IN / 2 + 255) / 256, 256>>>(features);
    dim3 wb(32, 8);
    wprep_kernel<<<dim3(D_LAT / 32, D_IN / 32), wb>>>(W_enc, OFF_ENC, D_IN, D_LAT);
    for (int l = 0; l < L_LAYERS; l++) {
        wprep_kernel<<<dim3(D_LAT / 32, D_LAT / 32), wb>>>(
            W_self + (size_t)l * WSZ, OFF_SELF(l), D_LAT, D_LAT);
        wprep_kernel<<<dim3(D_LAT / 32, D_LAT / 32), wb>>>(
            W_neigh + (size_t)l * WSZ, OFF_NEIGH(l), D_LAT, D_LAT);
    }
    wprep_kernel<<<dim3(D_OUT / 32, D_LAT / 32), wb>>>(W_out, OFF_OUT, D_LAT, D_OUT);

    const int MT = (N_NODES + 127) / 128;   // 157
    dim3 gLat(D_LAT / 128, MT);
    gemm_kernel<<<gLat, 256, GEMM_SMEM>>>(2, OFF_ENC, 0, 0, b_enc, 0, nullptr,
                                          N_NODES, D_LAT, 0);

    int cur = 0;
    for (int l = 0; l < L_LAYERS; l++) {
        gather_kernel<<<(N_NODES * 32 + 255) / 256, 256>>>(cur);
        gemm_kernel<<<gLat, 256, GEMM_SMEM>>>(cur, OFF_SELF(l), 1, OFF_NEIGH(l),
                                              b_comb + (size_t)l * D_LAT,
                                              1 - cur, nullptr,
                                              N_NODES, D_LAT, 1);
        cur = 1 - cur;
    }

    dim3 gOut(D_OUT / 128, MT);
    gemm_kernel<<<gOut, 256, GEMM_SMEM>>>(cur, OFF_OUT, 0, 0, b_out, -1, out,
                                          N_NODES, D_OUT, 0);
}

// round 9
// speedup vs baseline: 3.2526x; 1.0918x over previous
#include <cuda_runtime.h>
#include <cuda_bf16.h>
#include <cstdint>
#include <cstddef>

#define N_NODES 20000
#define N_EDGES 160000
#define D_IN    512
#define D_LAT   512
#define D_OUT   256
#define L_LAYERS 3
#define ROW_U4  (D_LAT / 8)
#define WSZ     (D_LAT * D_LAT)

// ---------------------------------------------------------------------------
// Scratch statics. Activations live only as bf16 (hi, lo) pairs.
// ---------------------------------------------------------------------------
__device__ uint4 g_hhi[2][(size_t)N_NODES * ROW_U4];
__device__ uint4 g_hlo[2][(size_t)N_NODES * ROW_U4];
__device__ uint4 g_agghi[(size_t)N_NODES * ROW_U4];
__device__ uint4 g_agglo[(size_t)N_NODES * ROW_U4];
__device__ uint4 g_fhi[(size_t)N_NODES * ROW_U4];
__device__ uint4 g_flo[(size_t)N_NODES * ROW_U4];
__device__ __nv_bfloat16 g_whi[7 * WSZ + D_LAT * D_OUT];
__device__ __nv_bfloat16 g_wlo[7 * WSZ + D_LAT * D_OUT];
__device__ int    g_degi[N_NODES];
__device__ int    g_off[N_NODES + 1];
__device__ int    g_bsum[128];
__device__ int    g_cursor[N_NODES];
__device__ float2 g_csr[N_EDGES];
__device__ int    g_el64;

#define OFF_ENC      0
#define OFF_SELF(l)  ((1 + (l)) * WSZ)
#define OFF_NEIGH(l) ((4 + (l)) * WSZ)
#define OFF_OUT      (7 * WSZ)

__device__ __forceinline__ float2 bf2f(uint32_t u) {
    __nv_bfloat162 b = *(__nv_bfloat162*)&u;
    return __bfloat1622float2(b);
}
__device__ __forceinline__ void split2(float x, float y, uint32_t& hi, uint32_t& lo) {
    __nv_bfloat162 hb = __floats2bfloat162_rn(x, y);
    float2 hf = __bfloat1622float2(hb);
    __nv_bfloat162 lb = __floats2bfloat162_rn(x - hf.x, y - hf.y);
    hi = *(uint32_t*)&hb;
    lo = *(uint32_t*)&lb;
}

// ---------------------------------------------------------------------------
// Edge dtype detection (int64 per reference vs int32 per JAX x64-off)
// ---------------------------------------------------------------------------
__global__ void detect_kernel(const int* __restrict__ el32) {
    if (threadIdx.x == 0) {
        int any = 0;
        for (int i = 0; i < 256; i++) any |= el32[2 * i + 1];
        g_el64 = (any == 0) ? 1 : 0;
    }
}

__device__ __forceinline__ void load_edge(const void* __restrict__ el,
                                          int e, int& s, int& d) {
    if (g_el64) {
        const long long* p = (const long long*)el;
        s = (int)p[2 * e + 0];
        d = (int)p[2 * e + 1];
    } else {
        const int* p = (const int*)el;
        s = p[2 * e + 0];
        d = p[2 * e + 1];
    }
}

// ---------------------------------------------------------------------------
// CSR build
// ---------------------------------------------------------------------------
__global__ void zero_degi_kernel() {
    int i = blockIdx.x * blockDim.x + threadIdx.x;
    if (i < N_NODES) g_degi[i] = 0;
}

__global__ void degi_kernel(const void* __restrict__ el) {
    int e = blockIdx.x * blockDim.x + threadIdx.x;
    if (e < N_EDGES) {
        int s, d;
        load_edge(el, e, s, d);
        atomicAdd(&g_degi[d], 1);
    }
}

__global__ void scan1_kernel() {
    __shared__ int sm[256];
    int tid = threadIdx.x;
    int i = blockIdx.x * 256 + tid;
    int v = (i < N_NODES) ? g_degi[i] : 0;
    sm[tid] = v;
    __syncthreads();
    for (int o = 1; o < 256; o <<= 1) {
        int x = (tid >= o) ? sm[tid - o] : 0;
        __syncthreads();
        sm[tid] += x;
        __syncthreads();
    }
    if (i < N_NODES) g_off[i] = sm[tid] - v;
    if (tid == 255) g_bsum[blockIdx.x] = sm[255];
}

__global__ void scan2_kernel(int nblocks) {
    if (threadIdx.x == 0 && blockIdx.x == 0) {
        int run = 0;
        for (int b = 0; b < nblocks; b++) {
            int t = g_bsum[b];
            g_bsum[b] = run;
            run += t;
        }
    }
}

__global__ void scan3_kernel() {
    int i = blockIdx.x * blockDim.x + threadIdx.x;
    if (i < N_NODES) {
        int o = g_off[i] + g_bsum[i >> 8];
        g_off[i] = o;
        g_cursor[i] = o;
    }
    if (i == 0) g_off[N_NODES] = N_EDGES;
}

__global__ void fill_kernel(const void* __restrict__ el) {
    int e = blockIdx.x * blockDim.x + threadIdx.x;
    if (e < N_EDGES) {
        int s, d;
        load_edge(el, e, s, d);
        float w = rsqrtf((float)(g_degi[d] + 1) * (float)(g_degi[s] + 1));
        int pos = atomicAdd(&g_cursor[d], 1);
        g_csr[pos] = make_float2(__int_as_float(s), w);
    }
}

// ---------------------------------------------------------------------------
// Feature split + weight prep (transpose fp32 [K][N] -> split bf16 [N][K])
// ---------------------------------------------------------------------------
__global__ void fsplit_kernel(const float* __restrict__ f) {
    int i = blockIdx.x * blockDim.x + threadIdx.x;
    const int n = N_NODES * D_IN / 2;
    if (i < n) {
        float2 v = ((const float2*)f)[i];
        uint32_t hi, lo;
        split2(v.x, v.y, hi, lo);
        ((uint32_t*)g_fhi)[i] = hi;
        ((uint32_t*)g_flo)[i] = lo;
    }
}

__global__ void wprep_kernel(const float* __restrict__ src, int dstOff,
                             int K, int N) {
    __shared__ float t[32][33];
    int tx = threadIdx.x, ty = threadIdx.y;
    int n0 = blockIdx.x * 32, k0 = blockIdx.y * 32;
#pragma unroll
    for (int j = 0; j < 4; j++)
        t[ty + j * 8][tx] = src[(size_t)(k0 + ty + j * 8) * N + n0 + tx];
    __syncthreads();
#pragma unroll
    for (int j = 0; j < 4; j++) {
        int n = n0 + ty + j * 8;
        int k = k0 + tx;
        float v = t[tx][ty + j * 8];
        __nv_bfloat16 hi = __float2bfloat16_rn(v);
        __nv_bfloat16 lo = __float2bfloat16_rn(v - __bfloat162float(hi));
        g_whi[(size_t)dstOff + (size_t)n * K + k] = hi;
        g_wlo[(size_t)dstOff + (size_t)n * K + k] = lo;
    }
}

// ---------------------------------------------------------------------------
// Gather: one warp per dst node; agg = sum w_e * (hi+lo)[src]
// ---------------------------------------------------------------------------
__global__ __launch_bounds__(256) void gather_kernel(int hsel) {
    int gw = (blockIdx.x * blockDim.x + threadIdx.x) >> 5;
    int lane = threadIdx.x & 31;
    if (gw >= N_NODES) return;
    int beg = g_off[gw], end = g_off[gw + 1];

    float acc[16];
#pragma unroll
    for (int i = 0; i < 16; i++) acc[i] = 0.0f;

    const uint4* Hh = g_hhi[hsel];
    const uint4* Hl = g_hlo[hsel];
    for (int i = beg; i < end; i++) {
        float2 er = g_csr[i];
        int s = __float_as_int(er.x);
        float w = er.y;
        const uint4* rh = Hh + (size_t)s * ROW_U4;
        const uint4* rl = Hl + (size_t)s * ROW_U4;
#pragma unroll
        for (int j = 0; j < 2; j++) {
            uint4 hv = rh[lane + 32 * j];
            uint4 lv = rl[lane + 32 * j];
            float2 a, b;
            a = bf2f(hv.x); b = bf2f(lv.x);
            acc[j * 8 + 0] += w * (a.x + b.x); acc[j * 8 + 1] += w * (a.y + b.y);
            a = bf2f(hv.y); b = bf2f(lv.y);
            acc[j * 8 + 2] += w * (a.x + b.x); acc[j * 8 + 3] += w * (a.y + b.y);
            a = bf2f(hv.z); b = bf2f(lv.z);
            acc[j * 8 + 4] += w * (a.x + b.x); acc[j * 8 + 5] += w * (a.y + b.y);
            a = bf2f(hv.w); b = bf2f(lv.w);
            acc[j * 8 + 6] += w * (a.x + b.x); acc[j * 8 + 7] += w * (a.y + b.y);
        }
    }
#pragma unroll
    for (int j = 0; j < 2; j++) {
        uint32_t ph[4], pl[4];
#pragma unroll
        for (int k = 0; k < 4; k++)
            split2(acc[j * 8 + k * 2], acc[j * 8 + k * 2 + 1], ph[k], pl[k]);
        g_agghi[(size_t)gw * ROW_U4 + lane + 32 * j] = make_uint4(ph[0], ph[1], ph[2], ph[3]);
        g_agglo[(size_t)gw * ROW_U4 + lane + 32 * j] = make_uint4(pl[0], pl[1], pl[2], pl[3]);
    }
}

// ---------------------------------------------------------------------------
// mma.sync GEMM, bf16 split-3:  C = [relu]( A*W (+ Agg*W2) + bias )
// 128x128 tile, BK=32 (2 k16 subs), 3-stage cp.async pipeline with ONE
// __syncthreads per chunk, ldmatrix fragments, XOR-swizzled smem.
// ---------------------------------------------------------------------------
#define GEMM_SMEM 98304
#define TS(s, t) ((uint32_t)(s) * 32768u + (uint32_t)(t) * 8192u)

__device__ __forceinline__ void cp16(uint32_t d, const void* s, int sz) {
    asm volatile("cp.async.cg.shared.global [%0], [%1], 16, %2;\n"
                 :: "r"(d), "l"(s), "r"(sz));
}

#define LDM4(r, addr)                                                         \
    asm volatile("ldmatrix.sync.aligned.m8n8.x4.shared.b16 "                  \
                 "{%0, %1, %2, %3}, [%4];"                                    \
                 : "=r"((r)[0]), "=r"((r)[1]), "=r"((r)[2]), "=r"((r)[3])     \
                 : "r"(addr))

#define MMA4(d, a, b0v, b1v)                                                  \
    asm volatile(                                                             \
        "mma.sync.aligned.m16n8k16.row.col.f32.bf16.bf16.f32 "                \
        "{%0,%1,%2,%3}, {%4,%5,%6,%7}, {%8,%9}, {%0,%1,%2,%3};\n"             \
        : "+f"((d)[0]), "+f"((d)[1]), "+f"((d)[2]), "+f"((d)[3])              \
        : "r"((a)[0]), "r"((a)[1]), "r"((a)[2]), "r"((a)[3]),                 \
          "r"(b0v), "r"(b1v))

__global__ __launch_bounds__(256, 2) void gemm_kernel(
    int aSel, int wOff, int useAgg, int wOff2,
    const float* __restrict__ bias,
    int cSel, float* __restrict__ extC,
    int M, int Ntot, int doRelu)
{
    extern __shared__ char smem[];
    uint32_t sb = (uint32_t)__cvta_generic_to_shared(smem);
    const int tid = threadIdx.x;
    const int wid = tid >> 5, lane = tid & 31;
    const int wm = (wid >> 2) * 64, wn = (wid & 3) * 32;
    const int m0 = blockIdx.y * 128, n0 = blockIdx.x * 128;
    const int li = lane & 7, quad = lane >> 3;

    float acc[4][4][4];
#pragma unroll
    for (int a = 0; a < 4; a++)
#pragma unroll
        for (int b = 0; b < 4; b++)
#pragma unroll
            for (int d = 0; d < 4; d++) acc[a][b][d] = 0.0f;

    // Lane-fixed fragment offsets (within a sub-tile).
    const int rA = (quad & 1) * 8 + li;
    const int sgA = quad >> 1;
    const int rB = (quad >> 1) * 8 + li;
    const int sgB = quad & 1;

    uint32_t offA[4], offB[2];
#pragma unroll
    for (int mt = 0; mt < 4; mt++) {
        int row = wm + mt * 16 + rA;
        offA[mt] = (uint32_t)(row * 32 + ((sgA ^ ((row >> 2) & 1)) * 16));
    }
#pragma unroll
    for (int ntp = 0; ntp < 2; ntp++) {
        int row = wn + ntp * 16 + rB;
        offB[ntp] = (uint32_t)(row * 32 + ((sgB ^ ((row >> 2) & 1)) * 16));
    }

    auto load_chunk = [&](int chunk, int stage) {
        const __nv_bfloat16 *Ah, *Al, *Bh, *Bl;
        if (chunk < 16) {
            Ah = (aSel == 2) ? (const __nv_bfloat16*)g_fhi
                             : (const __nv_bfloat16*)g_hhi[aSel];
            Al = (aSel == 2) ? (const __nv_bfloat16*)g_flo
                             : (const __nv_bfloat16*)g_hlo[aSel];
            Bh = g_whi + wOff;
            Bl = g_wlo + wOff;
        } else {
            Ah = (const __nv_bfloat16*)g_agghi;
            Al = (const __nv_bfloat16*)g_agglo;
            Bh = g_whi + wOff2;
            Bl = g_wlo + wOff2;
        }
        const int kk = (chunk & 15) * 32;
#pragma unroll
        for (int t = 0; t < 4; t++) {
            const __nv_bfloat16* src = (t == 0) ? Ah : (t == 1) ? Al
                                     : (t == 2) ? Bh : Bl;
            const bool isA = (t < 2);
#pragma unroll
            for (int i = 0; i < 2; i++) {
                int idx = tid + i * 256;          // 0..511
                int row = idx >> 2;
                int sub = (idx >> 1) & 1;
                int seg = idx & 1;
                int grow, valid;
                if (isA) {
                    int am = m0 + row;
                    valid = (am < M) ? 16 : 0;
                    grow = (am < M) ? am : 0;
                } else {
                    valid = 16;
                    grow = n0 + row;
                }
                const char* p = (const char*)(src + (size_t)grow * 512
                                              + kk + sub * 16 + seg * 8);
                uint32_t so = sb + TS(stage, t)
                            + (uint32_t)(sub * 4096 + row * 32
                                         + ((seg ^ ((row >> 2) & 1)) * 16));
                cp16(so, p, valid);
            }
        }
        asm volatile("cp.async.commit_group;\n");
    };

    const int NC = useAgg ? 32 : 16;
    load_chunk(0, 0);
    load_chunk(1, 1);

    for (int kt = 0; kt < NC; kt++) {
        int s = kt % 3;
        if (kt + 1 < NC) asm volatile("cp.async.wait_group 1;\n");
        else             asm volatile("cp.async.wait_group 0;\n");
        __syncthreads();   // chunk kt resident; all warps done reading kt-1

#pragma unroll
        for (int sub = 0; sub < 2; sub++) {
            uint32_t so = (uint32_t)(sub * 4096);
            uint32_t bh[2][4], bl[2][4];
#pragma unroll
            for (int ntp = 0; ntp < 2; ntp++) {
                LDM4(bh[ntp], sb + TS(s, 2) + so + offB[ntp]);
                LDM4(bl[ntp], sb + TS(s, 3) + so + offB[ntp]);
            }
#pragma unroll
            for (int mt = 0; mt < 4; mt++) {
                uint32_t ah[4], al[4];
                LDM4(ah, sb + TS(s, 0) + so + offA[mt]);
                LDM4(al, sb + TS(s, 1) + so + offA[mt]);
#pragma unroll
                for (int nt = 0; nt < 4; nt++) {
                    int ntp = nt >> 1, o = (nt & 1) * 2;
                    MMA4(acc[mt][nt], ah, bh[ntp][o], bh[ntp][o + 1]);
                    MMA4(acc[mt][nt], ah, bl[ntp][o], bl[ntp][o + 1]);
                    MMA4(acc[mt][nt], al, bh[ntp][o], bh[ntp][o + 1]);
                }
            }
        }
        if (kt + 2 < NC) load_chunk(kt + 2, (kt + 2) % 3);
    }

    // Epilogue
    const int g = lane >> 2, c = lane & 3;
#pragma unroll
    for (int mt = 0; mt < 4; mt++) {
#pragma unroll
        for (int nt = 0; nt < 4; nt++) {
            int gn = n0 + wn + nt * 8 + 2 * c;
            float b0 = bias[gn], b1 = bias[gn + 1];
#pragma unroll
            for (int half = 0; half < 2; half++) {
                int grow = m0 + wm + mt * 16 + g + half * 8;
                if (grow >= M) continue;
                float v0 = acc[mt][nt][half * 2 + 0] + b0;
                float v1 = acc[mt][nt][half * 2 + 1] + b1;
                if (doRelu) { v0 = fmaxf(v0, 0.f); v1 = fmaxf(v1, 0.f); }
                if (cSel >= 0) {
                    uint32_t hi, lo;
                    split2(v0, v1, hi, lo);
                    size_t idx = (size_t)grow * (D_LAT / 2) + (gn >> 1);
                    ((uint32_t*)g_hhi[cSel])[idx] = hi;
                    ((uint32_t*)g_hlo[cSel])[idx] = lo;
                } else {
                    *(float2*)&extC[(size_t)grow * Ntot + gn] = make_float2(v0, v1);
                }
            }
        }
    }
}

// ---------------------------------------------------------------------------
// Launch
// ---------------------------------------------------------------------------
extern "C" void kernel_launch(void* const* d_in, const int* in_sizes, int n_in,
                              void* d_out, int out_size) {
    const float* features = (const float*)d_in[0];
    const void*  edges    = d_in[1];
    const float* W_enc    = (const float*)d_in[2];
    const float* b_enc    = (const float*)d_in[3];
    const float* W_self   = (const float*)d_in[4];
    const float* W_neigh  = (const float*)d_in[5];
    const float* b_comb   = (const float*)d_in[6];
    const float* W_out    = (const float*)d_in[7];
    const float* b_out    = (const float*)d_in[8];
    float*       out      = (float*)d_out;

    cudaFuncSetAttribute(gemm_kernel,
                         cudaFuncAttributeMaxDynamicSharedMemorySize, GEMM_SMEM);

    const int SCAN_BLOCKS = (N_NODES + 255) / 256;

    detect_kernel<<<1, 32>>>((const int*)edges);
    zero_degi_kernel<<<SCAN_BLOCKS, 256>>>();
    degi_kernel<<<(N_EDGES + 255) / 256, 256>>>(edges);
    scan1_kernel<<<SCAN_BLOCKS, 256>>>();
    scan2_kernel<<<1, 32>>>(SCAN_BLOCKS);
    scan3_kernel<<<SCAN_BLOCKS, 256>>>();
    fill_kernel<<<(N_EDGES + 255) / 256, 256>>>(edges);

    fsplit_kernel<<<(N_NODES * D_IN / 2 + 255) / 256, 256>>>(features);
    dim3 wb(32, 8);
    wprep_kernel<<<dim3(D_LAT / 32, D_IN / 32), wb>>>(W_enc, OFF_ENC, D_IN, D_LAT);
    for (int l = 0; l < L_LAYERS; l++) {
        wprep_kernel<<<dim3(D_LAT / 32, D_LAT / 32), wb>>>(
            W_self + (size_t)l * WSZ, OFF_SELF(l), D_LAT, D_LAT);
        wprep_kernel<<<dim3(D_LAT / 32, D_LAT / 32), wb>>>(
            W_neigh + (size_t)l * WSZ, OFF_NEIGH(l), D_LAT, D_LAT);
    }
    wprep_kernel<<<dim3(D_OUT / 32, D_LAT / 32), wb>>>(W_out, OFF_OUT, D_LAT, D_OUT);

    const int MT = (N_NODES + 127) / 128;   // 157
    dim3 gLat(D_LAT / 128, MT);
    gemm_kernel<<<gLat, 256, GEMM_SMEM>>>(2, OFF_ENC, 0, 0, b_enc, 0, nullptr,
                                          N_NODES, D_LAT, 0);

    int cur = 0;
    for (int l = 0; l < L_LAYERS; l++) {
        gather_kernel<<<(N_NODES * 32 + 255) / 256, 256>>>(cur);
        gemm_kernel<<<gLat, 256, GEMM_SMEM>>>(cur, OFF_SELF(l), 1, OFF_NEIGH(l),
                                              b_comb + (size_t)l * D_LAT,
                                              1 - cur, nullptr,
                                              N_NODES, D_LAT, 1);
        cur = 1 - cur;
    }

    dim3 gOut(D_OUT / 128, MT);
    gemm_kernel<<<gOut, 256, GEMM_SMEM>>>(cur, OFF_OUT, 0, 0, b_out, -1, out,
                                          N_NODES, D_OUT, 0);
}